// round 5
// baseline (speedup 1.0000x reference)
#include <cuda_runtime.h>
#include <math.h>

#define N_NODES 50000
#define N_EDGES 800000

// ---------------- static device scratch (allocation-free rule) ----------------
__device__ float g_bufA[N_NODES * 256];
__device__ float g_bufB[N_NODES * 256];
__device__ int   g_rowbeg[N_NODES];
__device__ int   g_rowend[N_NODES];
__device__ int   g_cursor[N_NODES];
__device__ int   g_cnt[N_NODES];
__device__ float g_dinv[N_NODES];
__device__ int   g_col[N_EDGES];
__device__ int   g_total;

// ---------------- CSR build (scan-free: atomic segment allocation) ----------------
__global__ void zero_cnt_kernel() {
    int i = blockIdx.x * blockDim.x + threadIdx.x;
    if (i < N_NODES) g_cnt[i] = 0;
    if (i == 0) g_total = 0;
}

// edge_index is int32 (JAX x64 disabled: jnp.int64 -> int32)
__global__ void hist_kernel(const int* __restrict__ ei) {
    int e = blockIdx.x * blockDim.x + threadIdx.x;
    if (e < N_EDGES) {
        int d = ei[N_EDGES + e];
        atomicAdd(&g_cnt[d], 1);
    }
}

// degree norm + claim contiguous CSR segment per node via atomic bump
__global__ void alloc_kernel() {
    int i = blockIdx.x * blockDim.x + threadIdx.x;
    if (i < N_NODES) {
        int c = g_cnt[i];
        g_dinv[i] = rsqrtf((float)c + 1.0f);
        int beg = atomicAdd(&g_total, c);
        g_rowbeg[i] = beg;
        g_rowend[i] = beg + c;
        g_cursor[i] = beg;
    }
}

// norm is separable -> only src index stored per edge
__global__ void scatter_kernel(const int* __restrict__ ei) {
    int e = blockIdx.x * blockDim.x + threadIdx.x;
    if (e < N_EDGES) {
        int s = ei[e];
        int d = ei[N_EDGES + e];
        int pos = atomicAdd(&g_cursor[d], 1);
        g_col[pos] = s;
    }
}

// ---------------- packed dual-fp32 FMA (Blackwell FFMA2) ----------------
__device__ __forceinline__ void ffma2(unsigned long long& acc,
                                      unsigned long long a,
                                      unsigned long long b) {
    asm("fma.rn.f32x2 %0, %1, %2, %0;" : "+l"(acc) : "l"(a), "l"(b));
}
__device__ __forceinline__ void unpack2(unsigned long long v, float& lo, float& hi) {
    unsigned int l, h;
    asm("mov.b64 {%0, %1}, %2;" : "=r"(l), "=r"(h) : "l"(v));
    lo = __uint_as_float(l); hi = __uint_as_float(h);
}

// ============== GEMM64: C = A[NxK] @ W[Kx64-col-tile], BM=128 BN=64, 8x4 ==============
// Dup-B smem: chunk tx holds dup pairs of cols (4tx,4tx+1); chunk 16+tx -> (4tx+2,4tx+3)
template <int ACT, int SCALE>  // ACT: 0 none, 1 relu; SCALE: mult by dinv[row] after act
__global__ void __launch_bounds__(256) gemm64_kernel(
    const float* __restrict__ A, const float* __restrict__ W,
    const float* __restrict__ bias, float* __restrict__ C,
    int K, int Dout) {
    __shared__ __align__(16) float As[2][16][132];
    __shared__ __align__(16) float Bsd[2][16][128];
    const int t  = threadIdx.x;
    const int tx = t & 15, ty = t >> 4;
    const int rowBase = blockIdx.x * 128;
    const int colBase = blockIdx.y * 64;

    const int ar  = t >> 1;          // 0..127
    const int akc = (t & 1) * 8;     // 0 or 8
    const int bk  = ty;              // k-row for B load

    unsigned long long acc[4][4] = {};
    const int KT = K >> 4;

    float4 a0, a1, b0;
    {
        int grow = rowBase + ar;
        if (grow < N_NODES) {
            const float* ap = &A[(size_t)grow * K + akc];
            a0 = *reinterpret_cast<const float4*>(ap);
            a1 = *reinterpret_cast<const float4*>(ap + 4);
        } else { a0 = make_float4(0.f,0.f,0.f,0.f); a1 = a0; }
        b0 = *reinterpret_cast<const float4*>(&W[(size_t)bk * Dout + colBase + tx * 4]);
    }
    As[0][akc+0][ar] = a0.x; As[0][akc+1][ar] = a0.y;
    As[0][akc+2][ar] = a0.z; As[0][akc+3][ar] = a0.w;
    As[0][akc+4][ar] = a1.x; As[0][akc+5][ar] = a1.y;
    As[0][akc+6][ar] = a1.z; As[0][akc+7][ar] = a1.w;
    *reinterpret_cast<float4*>(&Bsd[0][bk][tx * 4])      = make_float4(b0.x, b0.x, b0.y, b0.y);
    *reinterpret_cast<float4*>(&Bsd[0][bk][64 + tx * 4]) = make_float4(b0.z, b0.z, b0.w, b0.w);
    __syncthreads();

    int cur = 0;
    for (int kt = 0; kt < KT; kt++) {
        if (kt + 1 < KT) {
            int k0 = (kt + 1) * 16;
            int grow = rowBase + ar;
            if (grow < N_NODES) {
                const float* ap = &A[(size_t)grow * K + k0 + akc];
                a0 = *reinterpret_cast<const float4*>(ap);
                a1 = *reinterpret_cast<const float4*>(ap + 4);
            } else { a0 = make_float4(0.f,0.f,0.f,0.f); a1 = a0; }
            b0 = *reinterpret_cast<const float4*>(&W[(size_t)(k0 + bk) * Dout + colBase + tx * 4]);
        }
        #pragma unroll
        for (int k = 0; k < 16; k++) {
            ulonglong2 ap0 = *reinterpret_cast<const ulonglong2*>(&As[cur][k][ty * 8]);
            ulonglong2 ap1 = *reinterpret_cast<const ulonglong2*>(&As[cur][k][ty * 8 + 4]);
            unsigned long long apk[4] = {ap0.x, ap0.y, ap1.x, ap1.y};
            ulonglong2 bd0 = *reinterpret_cast<const ulonglong2*>(&Bsd[cur][k][tx * 4]);
            ulonglong2 bd1 = *reinterpret_cast<const ulonglong2*>(&Bsd[cur][k][64 + tx * 4]);
            unsigned long long bd[4] = {bd0.x, bd0.y, bd1.x, bd1.y};
            #pragma unroll
            for (int ip = 0; ip < 4; ip++)
                #pragma unroll
                for (int j = 0; j < 4; j++)
                    ffma2(acc[ip][j], apk[ip], bd[j]);
        }
        if (kt + 1 < KT) {
            int nxt = cur ^ 1;
            As[nxt][akc+0][ar] = a0.x; As[nxt][akc+1][ar] = a0.y;
            As[nxt][akc+2][ar] = a0.z; As[nxt][akc+3][ar] = a0.w;
            As[nxt][akc+4][ar] = a1.x; As[nxt][akc+5][ar] = a1.y;
            As[nxt][akc+6][ar] = a1.z; As[nxt][akc+7][ar] = a1.w;
            *reinterpret_cast<float4*>(&Bsd[nxt][bk][tx * 4])      = make_float4(b0.x, b0.x, b0.y, b0.y);
            *reinterpret_cast<float4*>(&Bsd[nxt][bk][64 + tx * 4]) = make_float4(b0.z, b0.z, b0.w, b0.w);
            __syncthreads();
            cur = nxt;
        }
    }

    float4 bv = make_float4(0.f, 0.f, 0.f, 0.f);
    if (bias) bv = *reinterpret_cast<const float4*>(&bias[colBase + tx * 4]);
    #pragma unroll
    for (int ip = 0; ip < 4; ip++) {
        int r0 = rowBase + ty * 8 + 2 * ip;
        float4 v0, v1;
        float* vp0 = &v0.x; float* vp1 = &v1.x;
        #pragma unroll
        for (int j = 0; j < 4; j++) {
            float xlo, xhi;
            unpack2(acc[ip][j], xlo, xhi);
            float b = (&bv.x)[j];
            xlo += b; xhi += b;
            if (ACT == 1) { xlo = fmaxf(xlo, 0.f); xhi = fmaxf(xhi, 0.f); }
            vp0[j] = xlo; vp1[j] = xhi;
        }
        if (r0 < N_NODES) {
            if (SCALE) {
                float s = g_dinv[r0];
                v0.x *= s; v0.y *= s; v0.z *= s; v0.w *= s;
            }
            *reinterpret_cast<float4*>(&C[(size_t)r0 * Dout + colBase + tx * 4]) = v0;
        }
        if (r0 + 1 < N_NODES) {
            if (SCALE) {
                float s = g_dinv[r0 + 1];
                v1.x *= s; v1.y *= s; v1.z *= s; v1.w *= s;
            }
            *reinterpret_cast<float4*>(&C[(size_t)(r0 + 1) * Dout + colBase + tx * 4]) = v1;
        }
    }
}

// ============== GEMM128: BM=128 BN=128, 8x8 microtile, dup-B, dynamic smem ==============
// Dup-B chunks: tx->(8tx,8tx+1), 16+tx->(8tx+2,+3), 32+tx->(+4,+5), 48+tx->(+6,+7)
#define G128_SMEM_FLOATS (2*16*132 + 2*16*256)
template <int ACT, int SCALE>
__global__ void __launch_bounds__(256) gemm128_kernel(
    const float* __restrict__ A, const float* __restrict__ W,
    const float* __restrict__ bias, float* __restrict__ C,
    int K, int Dout) {
    extern __shared__ __align__(16) float sm[];
    float (*As)[16][132]  = reinterpret_cast<float(*)[16][132]>(sm);
    float (*Bsd)[16][256] = reinterpret_cast<float(*)[16][256]>(sm + 2*16*132);
    const int t  = threadIdx.x;
    const int tx = t & 15, ty = t >> 4;
    const int rowBase = blockIdx.x * 128;
    const int colBase = blockIdx.y * 128;

    const int ar  = t >> 1;
    const int akc = (t & 1) * 8;
    const int bk  = ty;

    unsigned long long acc[4][8] = {};
    const int KT = K >> 4;

    float4 a0, a1, b0, b1;
    {
        int grow = rowBase + ar;
        if (grow < N_NODES) {
            const float* ap = &A[(size_t)grow * K + akc];
            a0 = *reinterpret_cast<const float4*>(ap);
            a1 = *reinterpret_cast<const float4*>(ap + 4);
        } else { a0 = make_float4(0.f,0.f,0.f,0.f); a1 = a0; }
        const float* wp = &W[(size_t)bk * Dout + colBase + tx * 8];
        b0 = *reinterpret_cast<const float4*>(wp);
        b1 = *reinterpret_cast<const float4*>(wp + 4);
    }
    As[0][akc+0][ar] = a0.x; As[0][akc+1][ar] = a0.y;
    As[0][akc+2][ar] = a0.z; As[0][akc+3][ar] = a0.w;
    As[0][akc+4][ar] = a1.x; As[0][akc+5][ar] = a1.y;
    As[0][akc+6][ar] = a1.z; As[0][akc+7][ar] = a1.w;
    *reinterpret_cast<float4*>(&Bsd[0][bk][tx*4])       = make_float4(b0.x, b0.x, b0.y, b0.y);
    *reinterpret_cast<float4*>(&Bsd[0][bk][64 + tx*4])  = make_float4(b0.z, b0.z, b0.w, b0.w);
    *reinterpret_cast<float4*>(&Bsd[0][bk][128 + tx*4]) = make_float4(b1.x, b1.x, b1.y, b1.y);
    *reinterpret_cast<float4*>(&Bsd[0][bk][192 + tx*4]) = make_float4(b1.z, b1.z, b1.w, b1.w);
    __syncthreads();

    int cur = 0;
    for (int kt = 0; kt < KT; kt++) {
        if (kt + 1 < KT) {
            int k0 = (kt + 1) * 16;
            int grow = rowBase + ar;
            if (grow < N_NODES) {
                const float* ap = &A[(size_t)grow * K + k0 + akc];
                a0 = *reinterpret_cast<const float4*>(ap);
                a1 = *reinterpret_cast<const float4*>(ap + 4);
            } else { a0 = make_float4(0.f,0.f,0.f,0.f); a1 = a0; }
            const float* wp = &W[(size_t)(k0 + bk) * Dout + colBase + tx * 8];
            b0 = *reinterpret_cast<const float4*>(wp);
            b1 = *reinterpret_cast<const float4*>(wp + 4);
        }
        #pragma unroll
        for (int k = 0; k < 16; k++) {
            ulonglong2 ap0 = *reinterpret_cast<const ulonglong2*>(&As[cur][k][ty * 8]);
            ulonglong2 ap1 = *reinterpret_cast<const ulonglong2*>(&As[cur][k][ty * 8 + 4]);
            unsigned long long apk[4] = {ap0.x, ap0.y, ap1.x, ap1.y};
            ulonglong2 c0 = *reinterpret_cast<const ulonglong2*>(&Bsd[cur][k][tx*4]);
            ulonglong2 c1 = *reinterpret_cast<const ulonglong2*>(&Bsd[cur][k][64 + tx*4]);
            ulonglong2 c2 = *reinterpret_cast<const ulonglong2*>(&Bsd[cur][k][128 + tx*4]);
            ulonglong2 c3 = *reinterpret_cast<const ulonglong2*>(&Bsd[cur][k][192 + tx*4]);
            unsigned long long bd[8] = {c0.x, c0.y, c1.x, c1.y, c2.x, c2.y, c3.x, c3.y};
            #pragma unroll
            for (int ip = 0; ip < 4; ip++)
                #pragma unroll
                for (int j = 0; j < 8; j++)
                    ffma2(acc[ip][j], apk[ip], bd[j]);
        }
        if (kt + 1 < KT) {
            int nxt = cur ^ 1;
            As[nxt][akc+0][ar] = a0.x; As[nxt][akc+1][ar] = a0.y;
            As[nxt][akc+2][ar] = a0.z; As[nxt][akc+3][ar] = a0.w;
            As[nxt][akc+4][ar] = a1.x; As[nxt][akc+5][ar] = a1.y;
            As[nxt][akc+6][ar] = a1.z; As[nxt][akc+7][ar] = a1.w;
            *reinterpret_cast<float4*>(&Bsd[nxt][bk][tx*4])       = make_float4(b0.x, b0.x, b0.y, b0.y);
            *reinterpret_cast<float4*>(&Bsd[nxt][bk][64 + tx*4])  = make_float4(b0.z, b0.z, b0.w, b0.w);
            *reinterpret_cast<float4*>(&Bsd[nxt][bk][128 + tx*4]) = make_float4(b1.x, b1.x, b1.y, b1.y);
            *reinterpret_cast<float4*>(&Bsd[nxt][bk][192 + tx*4]) = make_float4(b1.z, b1.z, b1.w, b1.w);
            __syncthreads();
            cur = nxt;
        }
    }

    float bvals[8];
    #pragma unroll
    for (int j = 0; j < 8; j++) bvals[j] = 0.f;
    if (bias) {
        float4 ba = *reinterpret_cast<const float4*>(&bias[colBase + tx * 8]);
        float4 bb = *reinterpret_cast<const float4*>(&bias[colBase + tx * 8 + 4]);
        bvals[0]=ba.x; bvals[1]=ba.y; bvals[2]=ba.z; bvals[3]=ba.w;
        bvals[4]=bb.x; bvals[5]=bb.y; bvals[6]=bb.z; bvals[7]=bb.w;
    }
    #pragma unroll
    for (int ip = 0; ip < 4; ip++) {
        int r0 = rowBase + ty * 8 + 2 * ip;
        float lo[8], hi[8];
        #pragma unroll
        for (int j = 0; j < 8; j++) {
            unpack2(acc[ip][j], lo[j], hi[j]);
            lo[j] += bvals[j]; hi[j] += bvals[j];
            if (ACT == 1) { lo[j] = fmaxf(lo[j], 0.f); hi[j] = fmaxf(hi[j], 0.f); }
        }
        if (r0 < N_NODES) {
            float s = SCALE ? g_dinv[r0] : 1.0f;
            float* cp = &C[(size_t)r0 * Dout + colBase + tx * 8];
            *reinterpret_cast<float4*>(cp)     = make_float4(lo[0]*s, lo[1]*s, lo[2]*s, lo[3]*s);
            *reinterpret_cast<float4*>(cp + 4) = make_float4(lo[4]*s, lo[5]*s, lo[6]*s, lo[7]*s);
        }
        if (r0 + 1 < N_NODES) {
            float s = SCALE ? g_dinv[r0 + 1] : 1.0f;
            float* cp = &C[(size_t)(r0 + 1) * Dout + colBase + tx * 8];
            *reinterpret_cast<float4*>(cp)     = make_float4(hi[0]*s, hi[1]*s, hi[2]*s, hi[3]*s);
            *reinterpret_cast<float4*>(cp + 4) = make_float4(hi[4]*s, hi[5]*s, hi[6]*s, hi[7]*s);
        }
    }
}

// ---------------- Aggregation (separable norm): out[d] = f(dinv_d*(self + sum src) + b) ----------------
// PRESCALE: multiply output by dinv_d after activation (pre-scales for next agg)
template <int ACT, int PRESCALE>  // ACT: 0 none, 1 relu, 2 sigmoid
__global__ void __launch_bounds__(256) agg64_kernel(
    const float* __restrict__ in, float* __restrict__ out,
    const float* __restrict__ bias) {
    int warp = (blockIdx.x * blockDim.x + threadIdx.x) >> 5;
    if (warp >= N_NODES) return;
    int lane = threadIdx.x & 31;
    const int off = lane * 2;

    float2 self = *reinterpret_cast<const float2*>(in + (size_t)warp * 64 + off);
    float ax = self.x, ay = self.y;

    int e = g_rowbeg[warp], end = g_rowend[warp];
    for (; e + 4 <= end; e += 4) {
        int s0 = g_col[e], s1 = g_col[e+1], s2 = g_col[e+2], s3 = g_col[e+3];
        float2 p0 = *reinterpret_cast<const float2*>(in + (size_t)s0 * 64 + off);
        float2 p1 = *reinterpret_cast<const float2*>(in + (size_t)s1 * 64 + off);
        float2 p2 = *reinterpret_cast<const float2*>(in + (size_t)s2 * 64 + off);
        float2 p3 = *reinterpret_cast<const float2*>(in + (size_t)s3 * 64 + off);
        ax += p0.x; ay += p0.y;
        ax += p1.x; ay += p1.y;
        ax += p2.x; ay += p2.y;
        ax += p3.x; ay += p3.y;
    }
    for (; e < end; e++) {
        int si = g_col[e];
        float2 p = *reinterpret_cast<const float2*>(in + (size_t)si * 64 + off);
        ax += p.x; ay += p.y;
    }

    float dd = g_dinv[warp];
    ax *= dd; ay *= dd;
    if (bias) {
        const float2 b = *reinterpret_cast<const float2*>(bias + off);
        ax += b.x; ay += b.y;
    }
    if (ACT == 1) { ax = fmaxf(ax, 0.f); ay = fmaxf(ay, 0.f); }
    if (ACT == 2) {
        ax = 1.0f / (1.0f + expf(-ax));
        ay = 1.0f / (1.0f + expf(-ay));
    }
    if (PRESCALE) { ax *= dd; ay *= dd; }
    *reinterpret_cast<float2*>(out + (size_t)warp * 64 + off) = make_float2(ax, ay);
}

template <int ACT, int PRESCALE>
__global__ void __launch_bounds__(256) agg128_kernel(
    const float* __restrict__ in, float* __restrict__ out,
    const float* __restrict__ bias) {
    int warp = (blockIdx.x * blockDim.x + threadIdx.x) >> 5;
    if (warp >= N_NODES) return;
    int lane = threadIdx.x & 31;
    const int off = lane * 4;

    float4 self = *reinterpret_cast<const float4*>(in + (size_t)warp * 128 + off);
    float ax = self.x, ay = self.y, az = self.z, aw = self.w;

    int e = g_rowbeg[warp], end = g_rowend[warp];
    for (; e + 4 <= end; e += 4) {
        int s0 = g_col[e], s1 = g_col[e+1], s2 = g_col[e+2], s3 = g_col[e+3];
        float4 p0 = *reinterpret_cast<const float4*>(in + (size_t)s0 * 128 + off);
        float4 p1 = *reinterpret_cast<const float4*>(in + (size_t)s1 * 128 + off);
        float4 p2 = *reinterpret_cast<const float4*>(in + (size_t)s2 * 128 + off);
        float4 p3 = *reinterpret_cast<const float4*>(in + (size_t)s3 * 128 + off);
        ax += p0.x; ay += p0.y; az += p0.z; aw += p0.w;
        ax += p1.x; ay += p1.y; az += p1.z; aw += p1.w;
        ax += p2.x; ay += p2.y; az += p2.z; aw += p2.w;
        ax += p3.x; ay += p3.y; az += p3.z; aw += p3.w;
    }
    for (; e < end; e++) {
        int si = g_col[e];
        float4 p = *reinterpret_cast<const float4*>(in + (size_t)si * 128 + off);
        ax += p.x; ay += p.y; az += p.z; aw += p.w;
    }

    float dd = g_dinv[warp];
    ax *= dd; ay *= dd; az *= dd; aw *= dd;
    if (bias) {
        const float4 b = *reinterpret_cast<const float4*>(bias + off);
        ax += b.x; ay += b.y; az += b.z; aw += b.w;
    }
    if (ACT == 1) {
        ax = fmaxf(ax, 0.f); ay = fmaxf(ay, 0.f);
        az = fmaxf(az, 0.f); aw = fmaxf(aw, 0.f);
    }
    if (ACT == 2) {
        ax = 1.0f/(1.0f+expf(-ax)); ay = 1.0f/(1.0f+expf(-ay));
        az = 1.0f/(1.0f+expf(-az)); aw = 1.0f/(1.0f+expf(-aw));
    }
    if (PRESCALE) { ax *= dd; ay *= dd; az *= dd; aw *= dd; }
    *reinterpret_cast<float4*>(out + (size_t)warp * 128 + off) = make_float4(ax, ay, az, aw);
}

// ---------------- launch ----------------
extern "C" void kernel_launch(void* const* d_in, const int* in_sizes, int n_in,
                              void* d_out, int out_size) {
    const float* x  = (const float*)d_in[0];
    const int*   ei = (const int*)d_in[1];   // int32! (JAX x64 disabled)
    const float* W1 = (const float*)d_in[2],  *b1 = (const float*)d_in[3];
    const float* W2 = (const float*)d_in[4],  *b2 = (const float*)d_in[5];
    const float* W3 = (const float*)d_in[6],  *b3 = (const float*)d_in[7];
    const float* W4 = (const float*)d_in[8],  *b4 = (const float*)d_in[9];
    const float* W5 = (const float*)d_in[10], *b5 = (const float*)d_in[11];
    const float* W6 = (const float*)d_in[12], *b6 = (const float*)d_in[13];
    float* out = (float*)d_out;

    float *bufA, *bufB;
    cudaGetSymbolAddress((void**)&bufA, g_bufA);
    cudaGetSymbolAddress((void**)&bufB, g_bufB);

    const int TB = 256;
    const int nodeBlocks = (N_NODES + TB - 1) / TB;
    const int edgeBlocks = (N_EDGES + TB - 1) / TB;
    const int aggBlocks  = (N_NODES * 32 + TB - 1) / TB;
    const int gemmRows   = (N_NODES + 127) / 128;
    const int g128smem   = G128_SMEM_FLOATS * 4;

    cudaFuncSetAttribute(gemm128_kernel<1,1>, cudaFuncAttributeMaxDynamicSharedMemorySize, g128smem);
    cudaFuncSetAttribute(gemm128_kernel<1,0>, cudaFuncAttributeMaxDynamicSharedMemorySize, g128smem);
    cudaFuncSetAttribute(gemm128_kernel<0,1>, cudaFuncAttributeMaxDynamicSharedMemorySize, g128smem);

    // ---- preprocessing: degrees + CSR by dst (scan-free) ----
    zero_cnt_kernel<<<nodeBlocks, TB>>>();
    hist_kernel<<<edgeBlocks, TB>>>(ei);
    alloc_kernel<<<nodeBlocks, TB>>>();
    scatter_kernel<<<edgeBlocks, TB>>>(ei);

    // L1: gs = dinv .* (x@W1); agg1: dinv.*relu(dinv*(sum)+b1)   [prescale for agg2]
    gemm64_kernel<0,1><<<dim3(gemmRows, 1), TB>>>(x, W1, nullptr, bufA, 128, 64);
    agg64_kernel<1,1><<<aggBlocks, TB>>>(bufA, bufB, b1);

    // L2: agg2 (no act) -> GEMM2 bias+relu+scale (prescale for agg3)
    agg64_kernel<0,0><<<aggBlocks, TB>>>(bufB, bufA, nullptr);
    gemm128_kernel<1,1><<<dim3(gemmRows, 1), TB, g128smem>>>(bufA, W2, b2, bufB, 64, 128);

    // L3: agg3 -> GEMM3 bias+relu (no scale; next layer is GEMM-first)
    agg128_kernel<0,0><<<aggBlocks, TB>>>(bufB, bufA, nullptr);
    gemm128_kernel<1,0><<<dim3(gemmRows, 2), TB, g128smem>>>(bufA, W3, b3, bufB, 128, 256);

    // L4: GEMM4 scale -> agg4 relu+b4
    gemm128_kernel<0,1><<<dim3(gemmRows, 1), TB, g128smem>>>(bufB, W4, nullptr, bufA, 256, 128);
    agg128_kernel<1,0><<<aggBlocks, TB>>>(bufA, bufB, b4);

    // L5: GEMM5 scale -> agg5 relu+b5
    gemm64_kernel<0,1><<<dim3(gemmRows, 1), TB>>>(bufB, W5, nullptr, bufA, 128, 64);
    agg64_kernel<1,0><<<aggBlocks, TB>>>(bufA, bufB, b5);

    // L6: GEMM6 scale -> agg6 sigmoid+b6 -> d_out
    gemm64_kernel<0,1><<<dim3(gemmRows, 1), TB>>>(bufB, W6, nullptr, bufA, 64, 64);
    agg64_kernel<2,0><<<aggBlocks, TB>>>(bufA, out, b6);
}

// round 6
// speedup vs baseline: 1.1696x; 1.1696x over previous
#include <cuda_runtime.h>
#include <math.h>

#define N_NODES 50000
#define N_EDGES 800000

// ---------------- static device scratch (allocation-free rule) ----------------
__device__ float g_bufA[N_NODES * 256];
__device__ float g_bufB[N_NODES * 256];
__device__ int   g_rowbeg[N_NODES];
__device__ int   g_rowend[N_NODES];
__device__ int   g_cursor[N_NODES];
__device__ int   g_cnt[N_NODES];
__device__ float g_dinv[N_NODES];
__device__ int   g_col[N_EDGES];
__device__ int   g_total;

// ---------------- CSR build (scan-free: atomic segment allocation) ----------------
// edge_index is int32 (JAX x64 disabled: jnp.int64 -> int32)
__global__ void hist_kernel(const int* __restrict__ ei) {
    int e = blockIdx.x * blockDim.x + threadIdx.x;
    if (e < N_EDGES) {
        int d = ei[N_EDGES + e];
        atomicAdd(&g_cnt[d], 1);
    }
}

// degree norm + claim contiguous CSR segment per node via atomic bump
__global__ void alloc_kernel() {
    int i = blockIdx.x * blockDim.x + threadIdx.x;
    if (i < N_NODES) {
        int c = g_cnt[i];
        g_dinv[i] = rsqrtf((float)c + 1.0f);
        int beg = atomicAdd(&g_total, c);
        g_rowbeg[i] = beg;
        g_rowend[i] = beg + c;
        g_cursor[i] = beg;
    }
}

// norm is separable -> only src index stored per edge
__global__ void scatter_kernel(const int* __restrict__ ei) {
    int e = blockIdx.x * blockDim.x + threadIdx.x;
    if (e < N_EDGES) {
        int s = ei[e];
        int d = ei[N_EDGES + e];
        int pos = atomicAdd(&g_cursor[d], 1);
        g_col[pos] = s;
    }
}

// ---------------- packed dual-fp32 FMA (Blackwell FFMA2) ----------------
__device__ __forceinline__ void ffma2(unsigned long long& acc,
                                      unsigned long long a,
                                      unsigned long long b) {
    asm("fma.rn.f32x2 %0, %1, %2, %0;" : "+l"(acc) : "l"(a), "l"(b));
}
__device__ __forceinline__ unsigned long long pack2(unsigned int lo, unsigned int hi) {
    unsigned long long r;
    asm("mov.b64 %0, {%1, %2};" : "=l"(r) : "r"(lo), "r"(hi));
    return r;
}
__device__ __forceinline__ void unpack2(unsigned long long v, float& lo, float& hi) {
    unsigned int l, h;
    asm("mov.b64 {%0, %1}, %2;" : "=r"(l), "=r"(h) : "l"(v));
    lo = __uint_as_float(l); hi = __uint_as_float(h);
}

// ---------------- GEMM: C = A[N x K] @ W[K x Dout]  (+ bias, + act, + row scale) -----
// BM=128, BN=64, BK=16, 256 threads, 8x4 microtile via 4x4 packed-f32x2,
// double-buffered SMEM  (R4 configuration — measured best)
template <int ACT, int SCALE>  // ACT: 0 none, 1 relu; SCALE: mult by dinv[row] after act
__global__ void __launch_bounds__(256) gemm_kernel(
    const float* __restrict__ A, const float* __restrict__ W,
    const float* __restrict__ bias, float* __restrict__ C,
    int K, int Dout) {
    __shared__ __align__(16) float As[2][16][132];
    __shared__ __align__(16) float Bs[2][16][64];
    const int t  = threadIdx.x;
    const int tx = t & 15, ty = t >> 4;
    const int rowBase = blockIdx.x * 128;
    const int colBase = blockIdx.y * 64;

    const int ar  = t >> 1;          // 0..127
    const int akc = (t & 1) * 8;     // 0 or 8
    const int bk = ty, bc = tx * 4;

    unsigned long long acc[4][4] = {};
    const int KT = K >> 4;

    float4 a0, a1, b0;
    {
        int grow = rowBase + ar;
        if (grow < N_NODES) {
            const float* ap = &A[(size_t)grow * K + akc];
            a0 = *reinterpret_cast<const float4*>(ap);
            a1 = *reinterpret_cast<const float4*>(ap + 4);
        } else { a0 = make_float4(0.f,0.f,0.f,0.f); a1 = a0; }
        b0 = *reinterpret_cast<const float4*>(&W[(size_t)bk * Dout + colBase + bc]);
    }
    As[0][akc+0][ar] = a0.x; As[0][akc+1][ar] = a0.y;
    As[0][akc+2][ar] = a0.z; As[0][akc+3][ar] = a0.w;
    As[0][akc+4][ar] = a1.x; As[0][akc+5][ar] = a1.y;
    As[0][akc+6][ar] = a1.z; As[0][akc+7][ar] = a1.w;
    *reinterpret_cast<float4*>(&Bs[0][bk][bc]) = b0;
    __syncthreads();

    int cur = 0;
    for (int kt = 0; kt < KT; kt++) {
        if (kt + 1 < KT) {
            int k0 = (kt + 1) * 16;
            int grow = rowBase + ar;
            if (grow < N_NODES) {
                const float* ap = &A[(size_t)grow * K + k0 + akc];
                a0 = *reinterpret_cast<const float4*>(ap);
                a1 = *reinterpret_cast<const float4*>(ap + 4);
            } else { a0 = make_float4(0.f,0.f,0.f,0.f); a1 = a0; }
            b0 = *reinterpret_cast<const float4*>(&W[(size_t)(k0 + bk) * Dout + colBase + bc]);
        }
        #pragma unroll
        for (int k = 0; k < 16; k++) {
            ulonglong2 ap0 = *reinterpret_cast<const ulonglong2*>(&As[cur][k][ty * 8]);
            ulonglong2 ap1 = *reinterpret_cast<const ulonglong2*>(&As[cur][k][ty * 8 + 4]);
            unsigned long long apk[4] = {ap0.x, ap0.y, ap1.x, ap1.y};
            float4 bv = *reinterpret_cast<const float4*>(&Bs[cur][k][tx * 4]);
            unsigned long long brep[4] = {
                pack2(__float_as_uint(bv.x), __float_as_uint(bv.x)),
                pack2(__float_as_uint(bv.y), __float_as_uint(bv.y)),
                pack2(__float_as_uint(bv.z), __float_as_uint(bv.z)),
                pack2(__float_as_uint(bv.w), __float_as_uint(bv.w))
            };
            #pragma unroll
            for (int ip = 0; ip < 4; ip++)
                #pragma unroll
                for (int j = 0; j < 4; j++)
                    ffma2(acc[ip][j], apk[ip], brep[j]);
        }
        if (kt + 1 < KT) {
            int nxt = cur ^ 1;
            As[nxt][akc+0][ar] = a0.x; As[nxt][akc+1][ar] = a0.y;
            As[nxt][akc+2][ar] = a0.z; As[nxt][akc+3][ar] = a0.w;
            As[nxt][akc+4][ar] = a1.x; As[nxt][akc+5][ar] = a1.y;
            As[nxt][akc+6][ar] = a1.z; As[nxt][akc+7][ar] = a1.w;
            *reinterpret_cast<float4*>(&Bs[nxt][bk][bc]) = b0;
            __syncthreads();
            cur = nxt;
        }
    }

    float4 bv = make_float4(0.f, 0.f, 0.f, 0.f);
    if (bias) bv = *reinterpret_cast<const float4*>(&bias[colBase + tx * 4]);
    #pragma unroll
    for (int ip = 0; ip < 4; ip++) {
        int r0 = rowBase + ty * 8 + 2 * ip;
        float4 v0, v1;
        float* vp0 = &v0.x; float* vp1 = &v1.x;
        #pragma unroll
        for (int j = 0; j < 4; j++) {
            float xlo, xhi;
            unpack2(acc[ip][j], xlo, xhi);
            float b = (&bv.x)[j];
            xlo += b; xhi += b;
            if (ACT == 1) { xlo = fmaxf(xlo, 0.f); xhi = fmaxf(xhi, 0.f); }
            vp0[j] = xlo; vp1[j] = xhi;
        }
        if (r0 < N_NODES) {
            if (SCALE) {
                float s = g_dinv[r0];
                v0.x *= s; v0.y *= s; v0.z *= s; v0.w *= s;
            }
            *reinterpret_cast<float4*>(&C[(size_t)r0 * Dout + colBase + tx * 4]) = v0;
        }
        if (r0 + 1 < N_NODES) {
            if (SCALE) {
                float s = g_dinv[r0 + 1];
                v1.x *= s; v1.y *= s; v1.z *= s; v1.w *= s;
            }
            *reinterpret_cast<float4*>(&C[(size_t)(r0 + 1) * Dout + colBase + tx * 4]) = v1;
        }
    }
}

// ---------------- Aggregation (separable norm): out[d] = f(dinv_d*(self + sum src) + b) ----------------
// PRESCALE: multiply output by dinv_d after activation (pre-scales for next agg)
template <int ACT, int PRESCALE>  // ACT: 0 none, 1 relu, 2 sigmoid
__global__ void __launch_bounds__(256) agg64_kernel(
    const float* __restrict__ in, float* __restrict__ out,
    const float* __restrict__ bias) {
    int warp = (blockIdx.x * blockDim.x + threadIdx.x) >> 5;
    if (warp >= N_NODES) return;
    int lane = threadIdx.x & 31;
    const int off = lane * 2;

    float2 self = *reinterpret_cast<const float2*>(in + (size_t)warp * 64 + off);
    float ax = self.x, ay = self.y;

    int e = g_rowbeg[warp], end = g_rowend[warp];
    for (; e + 4 <= end; e += 4) {
        int s0 = g_col[e], s1 = g_col[e+1], s2 = g_col[e+2], s3 = g_col[e+3];
        float2 p0 = *reinterpret_cast<const float2*>(in + (size_t)s0 * 64 + off);
        float2 p1 = *reinterpret_cast<const float2*>(in + (size_t)s1 * 64 + off);
        float2 p2 = *reinterpret_cast<const float2*>(in + (size_t)s2 * 64 + off);
        float2 p3 = *reinterpret_cast<const float2*>(in + (size_t)s3 * 64 + off);
        ax += p0.x; ay += p0.y;
        ax += p1.x; ay += p1.y;
        ax += p2.x; ay += p2.y;
        ax += p3.x; ay += p3.y;
    }
    for (; e < end; e++) {
        int si = g_col[e];
        float2 p = *reinterpret_cast<const float2*>(in + (size_t)si * 64 + off);
        ax += p.x; ay += p.y;
    }

    float dd = g_dinv[warp];
    ax *= dd; ay *= dd;
    if (bias) {
        const float2 b = *reinterpret_cast<const float2*>(bias + off);
        ax += b.x; ay += b.y;
    }
    if (ACT == 1) { ax = fmaxf(ax, 0.f); ay = fmaxf(ay, 0.f); }
    if (ACT == 2) {
        ax = 1.0f / (1.0f + expf(-ax));
        ay = 1.0f / (1.0f + expf(-ay));
    }
    if (PRESCALE) { ax *= dd; ay *= dd; }
    *reinterpret_cast<float2*>(out + (size_t)warp * 64 + off) = make_float2(ax, ay);
}

template <int ACT, int PRESCALE>
__global__ void __launch_bounds__(256) agg128_kernel(
    const float* __restrict__ in, float* __restrict__ out,
    const float* __restrict__ bias) {
    int warp = (blockIdx.x * blockDim.x + threadIdx.x) >> 5;
    if (warp >= N_NODES) return;
    int lane = threadIdx.x & 31;
    const int off = lane * 4;

    float4 self = *reinterpret_cast<const float4*>(in + (size_t)warp * 128 + off);
    float ax = self.x, ay = self.y, az = self.z, aw = self.w;

    int e = g_rowbeg[warp], end = g_rowend[warp];
    for (; e + 4 <= end; e += 4) {
        int s0 = g_col[e], s1 = g_col[e+1], s2 = g_col[e+2], s3 = g_col[e+3];
        float4 p0 = *reinterpret_cast<const float4*>(in + (size_t)s0 * 128 + off);
        float4 p1 = *reinterpret_cast<const float4*>(in + (size_t)s1 * 128 + off);
        float4 p2 = *reinterpret_cast<const float4*>(in + (size_t)s2 * 128 + off);
        float4 p3 = *reinterpret_cast<const float4*>(in + (size_t)s3 * 128 + off);
        ax += p0.x; ay += p0.y; az += p0.z; aw += p0.w;
        ax += p1.x; ay += p1.y; az += p1.z; aw += p1.w;
        ax += p2.x; ay += p2.y; az += p2.z; aw += p2.w;
        ax += p3.x; ay += p3.y; az += p3.z; aw += p3.w;
    }
    for (; e < end; e++) {
        int si = g_col[e];
        float4 p = *reinterpret_cast<const float4*>(in + (size_t)si * 128 + off);
        ax += p.x; ay += p.y; az += p.z; aw += p.w;
    }

    float dd = g_dinv[warp];
    ax *= dd; ay *= dd; az *= dd; aw *= dd;
    if (bias) {
        const float4 b = *reinterpret_cast<const float4*>(bias + off);
        ax += b.x; ay += b.y; az += b.z; aw += b.w;
    }
    if (ACT == 1) {
        ax = fmaxf(ax, 0.f); ay = fmaxf(ay, 0.f);
        az = fmaxf(az, 0.f); aw = fmaxf(aw, 0.f);
    }
    if (ACT == 2) {
        ax = 1.0f/(1.0f+expf(-ax)); ay = 1.0f/(1.0f+expf(-ay));
        az = 1.0f/(1.0f+expf(-az)); aw = 1.0f/(1.0f+expf(-aw));
    }
    if (PRESCALE) { ax *= dd; ay *= dd; az *= dd; aw *= dd; }
    *reinterpret_cast<float4*>(out + (size_t)warp * 128 + off) = make_float4(ax, ay, az, aw);
}

// ---------------- launch ----------------
extern "C" void kernel_launch(void* const* d_in, const int* in_sizes, int n_in,
                              void* d_out, int out_size) {
    const float* x  = (const float*)d_in[0];
    const int*   ei = (const int*)d_in[1];   // int32! (JAX x64 disabled)
    const float* W1 = (const float*)d_in[2],  *b1 = (const float*)d_in[3];
    const float* W2 = (const float*)d_in[4],  *b2 = (const float*)d_in[5];
    const float* W3 = (const float*)d_in[6],  *b3 = (const float*)d_in[7];
    const float* W4 = (const float*)d_in[8],  *b4 = (const float*)d_in[9];
    const float* W5 = (const float*)d_in[10], *b5 = (const float*)d_in[11];
    const float* W6 = (const float*)d_in[12], *b6 = (const float*)d_in[13];
    float* out = (float*)d_out;

    float *bufA, *bufB;
    cudaGetSymbolAddress((void**)&bufA, g_bufA);
    cudaGetSymbolAddress((void**)&bufB, g_bufB);
    void *cntPtr, *totPtr;
    cudaGetSymbolAddress(&cntPtr, g_cnt);
    cudaGetSymbolAddress(&totPtr, g_total);

    const int TB = 256;
    const int nodeBlocks = (N_NODES + TB - 1) / TB;
    const int edgeBlocks = (N_EDGES + TB - 1) / TB;
    const int aggBlocks  = (N_NODES * 32 + TB - 1) / TB;
    const int gemmRows   = (N_NODES + 127) / 128;

    // ---- preprocessing: degrees + CSR by dst (scan-free) ----
    cudaMemsetAsync(cntPtr, 0, N_NODES * sizeof(int));
    cudaMemsetAsync(totPtr, 0, sizeof(int));
    hist_kernel<<<edgeBlocks, TB>>>(ei);
    alloc_kernel<<<nodeBlocks, TB>>>();
    scatter_kernel<<<edgeBlocks, TB>>>(ei);

    // L1: hs = dinv .* (x@W1); agg: dinv.*relu(dinv*(sum)+b1)   [prescaled for L2 agg]
    gemm_kernel<0,1><<<dim3(gemmRows, 1), TB>>>(x, W1, nullptr, bufA, 128, 64);
    agg64_kernel<1,1><<<aggBlocks, TB>>>(bufA, bufB, b1);

    // L2: agg (no act) -> GEMM bias+relu+scale (prescaled for L3 agg)
    agg64_kernel<0,0><<<aggBlocks, TB>>>(bufB, bufA, nullptr);
    gemm_kernel<1,1><<<dim3(gemmRows, 2), TB>>>(bufA, W2, b2, bufB, 64, 128);

    // L3: agg -> GEMM bias+relu (no scale; L4 is GEMM-first)
    agg128_kernel<0,0><<<aggBlocks, TB>>>(bufB, bufA, nullptr);
    gemm_kernel<1,0><<<dim3(gemmRows, 4), TB>>>(bufA, W3, b3, bufB, 128, 256);

    // L4: GEMM scale -> agg relu+b4
    gemm_kernel<0,1><<<dim3(gemmRows, 2), TB>>>(bufB, W4, nullptr, bufA, 256, 128);
    agg128_kernel<1,0><<<aggBlocks, TB>>>(bufA, bufB, b4);

    // L5: GEMM scale -> agg relu+b5
    gemm_kernel<0,1><<<dim3(gemmRows, 1), TB>>>(bufB, W5, nullptr, bufA, 128, 64);
    agg64_kernel<1,0><<<aggBlocks, TB>>>(bufA, bufB, b5);

    // L6: GEMM scale -> agg sigmoid+b6 -> d_out
    gemm_kernel<0,1><<<dim3(gemmRows, 1), TB>>>(bufB, W6, nullptr, bufA, 64, 64);
    agg64_kernel<2,0><<<aggBlocks, TB>>>(bufA, out, b6);
}

// round 10
// speedup vs baseline: 1.3597x; 1.1625x over previous
#include <cuda_runtime.h>
#include <cuda_bf16.h>
#include <math.h>
#include <stdint.h>

#define N_NODES 50000
#define N_EDGES 800000
#define W_TOTAL 94208  // sum of K*Dout over 6 layers

// ---------------- static device scratch (allocation-free rule) ----------------
__device__ float g_bufA[N_NODES * 256];
__device__ float g_bufB[N_NODES * 256];
__device__ int   g_rowbeg[N_NODES];
__device__ int   g_rowend[N_NODES];
__device__ int   g_cursor[N_NODES];
__device__ int   g_cnt[N_NODES];
__device__ float g_dinv[N_NODES];
__device__ int   g_col[N_EDGES];
__device__ int   g_total;
__device__ unsigned short g_whi[W_TOTAL];  // bf16 hi, transposed [Dout][K]
__device__ unsigned short g_wlo[W_TOTAL];  // bf16 lo

// ---------------- CSR build (scan-free) ----------------
__global__ void hist_kernel(const int* __restrict__ ei) {
    int e = blockIdx.x * blockDim.x + threadIdx.x;
    if (e < N_EDGES) atomicAdd(&g_cnt[ei[N_EDGES + e]], 1);
}

__global__ void alloc_kernel() {
    int i = blockIdx.x * blockDim.x + threadIdx.x;
    if (i < N_NODES) {
        int c = g_cnt[i];
        g_dinv[i] = rsqrtf((float)c + 1.0f);
        int beg = atomicAdd(&g_total, c);
        g_rowbeg[i] = beg;
        g_rowend[i] = beg + c;
        g_cursor[i] = beg;
    }
}

__global__ void scatter_kernel(const int* __restrict__ ei) {
    int e = blockIdx.x * blockDim.x + threadIdx.x;
    if (e < N_EDGES) {
        int s = ei[e];
        int d = ei[N_EDGES + e];
        int pos = atomicAdd(&g_cursor[d], 1);
        g_col[pos] = s;
    }
}

// ---------------- W prep: fp32 [K][Dout] -> bf16 hi/lo transposed [Dout][K] ----------------
__global__ void wprep_kernel(const float* __restrict__ W, int K, int Dout, int off) {
    int i = blockIdx.x * blockDim.x + threadIdx.x;
    if (i < K * Dout) {
        int k = i / Dout, n = i % Dout;
        float v = W[i];
        __nv_bfloat16 h = __float2bfloat16(v);
        float r = v - __bfloat162float(h);
        g_whi[off + n * K + k] = __bfloat16_as_ushort(h);
        g_wlo[off + n * K + k] = __bfloat16_as_ushort(__float2bfloat16(r));
    }
}

// ---------------- warp MMA: m16n8k16 bf16 -> fp32 (sm_80+ PTX, compiles on sm_100) ----------
__device__ __forceinline__ void mma16816(float* d, const uint32_t* a, const uint32_t* b) {
    asm volatile(
        "mma.sync.aligned.m16n8k16.row.col.f32.bf16.bf16.f32 "
        "{%0,%1,%2,%3}, {%4,%5,%6,%7}, {%8,%9}, {%0,%1,%2,%3};"
        : "+f"(d[0]), "+f"(d[1]), "+f"(d[2]), "+f"(d[3])
        : "r"(a[0]), "r"(a[1]), "r"(a[2]), "r"(a[3]), "r"(b[0]), "r"(b[1]));
}

// ---------------- tensor-core GEMM: C = A[NxK] @ W[KxDout] (bf16-split, 3 MMAs) ----------
// BM=128, BN=64, BK=32. 8 warps in 4x2; warp tile 32x32 (2 m-frags x 4 n-frags).
// Fragments use the k-permutation {4tc..4tc+3} on BOTH operands (dot-product invariant)
// so every fragment load is one contiguous 8-byte LDS.
template <int ACT, int SCALE>  // ACT: 0 none, 1 relu; SCALE: mult by dinv[row] after act
__global__ void __launch_bounds__(256) mma_gemm_kernel(
    const float* __restrict__ A,
    const unsigned short* __restrict__ whi, const unsigned short* __restrict__ wlo,
    const float* __restrict__ bias, float* __restrict__ C,
    int K, int Dout) {
    constexpr int BK = 32;
    constexpr int SA = 40;  // row stride in halves (80B: 16B-aligned, bank-staggered)
    __shared__ __align__(16) unsigned short Ah[128 * SA];
    __shared__ __align__(16) unsigned short Al[128 * SA];
    __shared__ __align__(16) unsigned short Bh[64 * SA];
    __shared__ __align__(16) unsigned short Bl[64 * SA];

    const int t = threadIdx.x;
    const int lane = t & 31, wid = t >> 5;
    const int g = lane >> 2, tc = lane & 3;
    const int warpRow = wid & 3, warpCol = wid >> 2;
    const int rowBase = blockIdx.x * 128;
    const int colBase = blockIdx.y * 64;

    float d[2][4][4] = {};

    for (int kb = 0; kb < K; kb += BK) {
        // ---- stage A tile [128][BK] with fused fp32 -> bf16 hi/lo split ----
        for (int task = t; task < 128 * (BK / 8); task += 256) {
            int row = task >> 2;             // BK/8 == 4
            int col0 = (task & 3) * 8;
            float v[8];
            int grow = rowBase + row;
            if (grow < N_NODES) {
                const float* p = A + (size_t)grow * K + kb + col0;
                float4 x0 = *reinterpret_cast<const float4*>(p);
                float4 x1 = *reinterpret_cast<const float4*>(p + 4);
                v[0]=x0.x; v[1]=x0.y; v[2]=x0.z; v[3]=x0.w;
                v[4]=x1.x; v[5]=x1.y; v[6]=x1.z; v[7]=x1.w;
            } else {
                #pragma unroll
                for (int j = 0; j < 8; j++) v[j] = 0.f;
            }
            unsigned int hp[4], lp[4];
            #pragma unroll
            for (int j = 0; j < 4; j++) {
                __nv_bfloat16 h0 = __float2bfloat16(v[2*j]);
                __nv_bfloat16 h1 = __float2bfloat16(v[2*j+1]);
                float r0 = v[2*j]   - __bfloat162float(h0);
                float r1 = v[2*j+1] - __bfloat162float(h1);
                hp[j] = (unsigned int)__bfloat16_as_ushort(h0)
                      | ((unsigned int)__bfloat16_as_ushort(h1) << 16);
                lp[j] = (unsigned int)__bfloat16_as_ushort(__float2bfloat16(r0))
                      | ((unsigned int)__bfloat16_as_ushort(__float2bfloat16(r1)) << 16);
            }
            *reinterpret_cast<uint4*>(&Ah[row * SA + col0]) = make_uint4(hp[0],hp[1],hp[2],hp[3]);
            *reinterpret_cast<uint4*>(&Al[row * SA + col0]) = make_uint4(lp[0],lp[1],lp[2],lp[3]);
        }
        // ---- stage B tile [64][BK] from pre-split W^T ([Dout][K] bf16) ----
        for (int task = t; task < 64 * (BK / 8); task += 256) {
            int n = task >> 2;
            int col0 = (task & 3) * 8;
            size_t src = (size_t)(colBase + n) * K + kb + col0;
            *reinterpret_cast<uint4*>(&Bh[n * SA + col0]) =
                *reinterpret_cast<const uint4*>(whi + src);
            *reinterpret_cast<uint4*>(&Bl[n * SA + col0]) =
                *reinterpret_cast<const uint4*>(wlo + src);
        }
        __syncthreads();

        #pragma unroll
        for (int ks = 0; ks < 2; ks++) {
            const int kk = ks * 16;
            uint32_t ahf[2][4], alf[2][4];
            #pragma unroll
            for (int i = 0; i < 2; i++) {
                int r0 = warpRow * 32 + i * 16 + g;
                uint2 x = *reinterpret_cast<const uint2*>(&Ah[r0 * SA + kk + tc * 4]);
                uint2 y = *reinterpret_cast<const uint2*>(&Ah[(r0 + 8) * SA + kk + tc * 4]);
                ahf[i][0] = x.x; ahf[i][2] = x.y; ahf[i][1] = y.x; ahf[i][3] = y.y;
                uint2 xl = *reinterpret_cast<const uint2*>(&Al[r0 * SA + kk + tc * 4]);
                uint2 yl = *reinterpret_cast<const uint2*>(&Al[(r0 + 8) * SA + kk + tc * 4]);
                alf[i][0] = xl.x; alf[i][2] = xl.y; alf[i][1] = yl.x; alf[i][3] = yl.y;
            }
            uint32_t bhf[4][2], blf[4][2];
            #pragma unroll
            for (int j = 0; j < 4; j++) {
                int n = warpCol * 32 + j * 8 + g;
                uint2 x = *reinterpret_cast<const uint2*>(&Bh[n * SA + kk + tc * 4]);
                bhf[j][0] = x.x; bhf[j][1] = x.y;
                uint2 y = *reinterpret_cast<const uint2*>(&Bl[n * SA + kk + tc * 4]);
                blf[j][0] = y.x; blf[j][1] = y.y;
            }
            #pragma unroll
            for (int i = 0; i < 2; i++)
                #pragma unroll
                for (int j = 0; j < 4; j++) {
                    mma16816(d[i][j], ahf[i], bhf[j]);
                    mma16816(d[i][j], alf[i], bhf[j]);
                    mma16816(d[i][j], ahf[i], blf[j]);
                }
        }
        __syncthreads();
    }

    // ---- epilogue: d frag (i,j): rows r0,r0+8; cols col,col+1 ----
    #pragma unroll
    for (int i = 0; i < 2; i++) {
        int r0 = rowBase + warpRow * 32 + i * 16 + g;
        int r1 = r0 + 8;
        float s0 = 1.0f, s1 = 1.0f;
        if (SCALE) {
            if (r0 < N_NODES) s0 = g_dinv[r0];
            if (r1 < N_NODES) s1 = g_dinv[r1];
        }
        #pragma unroll
        for (int j = 0; j < 4; j++) {
            int col = colBase + warpCol * 32 + j * 8 + tc * 2;
            float b0 = 0.f, b1 = 0.f;
            if (bias) { b0 = bias[col]; b1 = bias[col + 1]; }
            float v0 = d[i][j][0] + b0, v1 = d[i][j][1] + b1;
            float v2 = d[i][j][2] + b0, v3 = d[i][j][3] + b1;
            if (ACT == 1) {
                v0 = fmaxf(v0, 0.f); v1 = fmaxf(v1, 0.f);
                v2 = fmaxf(v2, 0.f); v3 = fmaxf(v3, 0.f);
            }
            if (r0 < N_NODES)
                *reinterpret_cast<float2*>(&C[(size_t)r0 * Dout + col]) =
                    make_float2(v0 * s0, v1 * s0);
            if (r1 < N_NODES)
                *reinterpret_cast<float2*>(&C[(size_t)r1 * Dout + col]) =
                    make_float2(v2 * s1, v3 * s1);
        }
    }
}

// ---------------- Aggregation (separable norm) ----------------
template <int ACT, int PRESCALE>  // ACT: 0 none, 1 relu, 2 sigmoid
__global__ void __launch_bounds__(256) agg64_kernel(
    const float* __restrict__ in, float* __restrict__ out,
    const float* __restrict__ bias) {
    int warp = (blockIdx.x * blockDim.x + threadIdx.x) >> 5;
    if (warp >= N_NODES) return;
    int lane = threadIdx.x & 31;
    const int off = lane * 2;

    float2 self = *reinterpret_cast<const float2*>(in + (size_t)warp * 64 + off);
    float ax = self.x, ay = self.y;

    int e = g_rowbeg[warp], end = g_rowend[warp];
    for (; e + 4 <= end; e += 4) {
        int s0 = g_col[e], s1 = g_col[e+1], s2 = g_col[e+2], s3 = g_col[e+3];
        float2 p0 = *reinterpret_cast<const float2*>(in + (size_t)s0 * 64 + off);
        float2 p1 = *reinterpret_cast<const float2*>(in + (size_t)s1 * 64 + off);
        float2 p2 = *reinterpret_cast<const float2*>(in + (size_t)s2 * 64 + off);
        float2 p3 = *reinterpret_cast<const float2*>(in + (size_t)s3 * 64 + off);
        ax += p0.x; ay += p0.y;
        ax += p1.x; ay += p1.y;
        ax += p2.x; ay += p2.y;
        ax += p3.x; ay += p3.y;
    }
    for (; e < end; e++) {
        int si = g_col[e];
        float2 p = *reinterpret_cast<const float2*>(in + (size_t)si * 64 + off);
        ax += p.x; ay += p.y;
    }

    float dd = g_dinv[warp];
    ax *= dd; ay *= dd;
    if (bias) {
        const float2 b = *reinterpret_cast<const float2*>(bias + off);
        ax += b.x; ay += b.y;
    }
    if (ACT == 1) { ax = fmaxf(ax, 0.f); ay = fmaxf(ay, 0.f); }
    if (ACT == 2) {
        ax = 1.0f / (1.0f + expf(-ax));
        ay = 1.0f / (1.0f + expf(-ay));
    }
    if (PRESCALE) { ax *= dd; ay *= dd; }
    *reinterpret_cast<float2*>(out + (size_t)warp * 64 + off) = make_float2(ax, ay);
}

template <int ACT, int PRESCALE>
__global__ void __launch_bounds__(256) agg128_kernel(
    const float* __restrict__ in, float* __restrict__ out,
    const float* __restrict__ bias) {
    int warp = (blockIdx.x * blockDim.x + threadIdx.x) >> 5;
    if (warp >= N_NODES) return;
    int lane = threadIdx.x & 31;
    const int off = lane * 4;

    float4 self = *reinterpret_cast<const float4*>(in + (size_t)warp * 128 + off);
    float ax = self.x, ay = self.y, az = self.z, aw = self.w;

    int e = g_rowbeg[warp], end = g_rowend[warp];
    for (; e + 4 <= end; e += 4) {
        int s0 = g_col[e], s1 = g_col[e+1], s2 = g_col[e+2], s3 = g_col[e+3];
        float4 p0 = *reinterpret_cast<const float4*>(in + (size_t)s0 * 128 + off);
        float4 p1 = *reinterpret_cast<const float4*>(in + (size_t)s1 * 128 + off);
        float4 p2 = *reinterpret_cast<const float4*>(in + (size_t)s2 * 128 + off);
        float4 p3 = *reinterpret_cast<const float4*>(in + (size_t)s3 * 128 + off);
        ax += p0.x; ay += p0.y; az += p0.z; aw += p0.w;
        ax += p1.x; ay += p1.y; az += p1.z; aw += p1.w;
        ax += p2.x; ay += p2.y; az += p2.z; aw += p2.w;
        ax += p3.x; ay += p3.y; az += p3.z; aw += p3.w;
    }
    for (; e < end; e++) {
        int si = g_col[e];
        float4 p = *reinterpret_cast<const float4*>(in + (size_t)si * 128 + off);
        ax += p.x; ay += p.y; az += p.z; aw += p.w;
    }

    float dd = g_dinv[warp];
    ax *= dd; ay *= dd; az *= dd; aw *= dd;
    if (bias) {
        const float4 b = *reinterpret_cast<const float4*>(bias + off);
        ax += b.x; ay += b.y; az += b.z; aw += b.w;
    }
    if (ACT == 1) {
        ax = fmaxf(ax, 0.f); ay = fmaxf(ay, 0.f);
        az = fmaxf(az, 0.f); aw = fmaxf(aw, 0.f);
    }
    if (ACT == 2) {
        ax = 1.0f/(1.0f+expf(-ax)); ay = 1.0f/(1.0f+expf(-ay));
        az = 1.0f/(1.0f+expf(-az)); aw = 1.0f/(1.0f+expf(-aw));
    }
    if (PRESCALE) { ax *= dd; ay *= dd; az *= dd; aw *= dd; }
    *reinterpret_cast<float4*>(out + (size_t)warp * 128 + off) = make_float4(ax, ay, az, aw);
}

// ---------------- launch ----------------
extern "C" void kernel_launch(void* const* d_in, const int* in_sizes, int n_in,
                              void* d_out, int out_size) {
    const float* x  = (const float*)d_in[0];
    const int*   ei = (const int*)d_in[1];   // int32! (JAX x64 disabled)
    const float* W1 = (const float*)d_in[2],  *b1 = (const float*)d_in[3];
    const float* W2 = (const float*)d_in[4],  *b2 = (const float*)d_in[5];
    const float* W3 = (const float*)d_in[6],  *b3 = (const float*)d_in[7];
    const float* W4 = (const float*)d_in[8],  *b4 = (const float*)d_in[9];
    const float* W5 = (const float*)d_in[10], *b5 = (const float*)d_in[11];
    const float* W6 = (const float*)d_in[12], *b6 = (const float*)d_in[13];
    float* out = (float*)d_out;

    float *bufA, *bufB;
    cudaGetSymbolAddress((void**)&bufA, g_bufA);
    cudaGetSymbolAddress((void**)&bufB, g_bufB);
    void *cntPtr, *totPtr;
    cudaGetSymbolAddress(&cntPtr, g_cnt);
    cudaGetSymbolAddress(&totPtr, g_total);
    unsigned short *whi, *wlo;
    cudaGetSymbolAddress((void**)&whi, g_whi);
    cudaGetSymbolAddress((void**)&wlo, g_wlo);

    const int TB = 256;
    const int nodeBlocks = (N_NODES + TB - 1) / TB;
    const int edgeBlocks = (N_EDGES + TB - 1) / TB;
    const int aggBlocks  = (N_NODES * 32 + TB - 1) / TB;
    const int gemmRows   = (N_NODES + 127) / 128;

    // W layer offsets within g_whi/g_wlo
    const int wo1 = 0, wo2 = 8192, wo3 = 16384, wo4 = 49152, wo5 = 81920, wo6 = 90112;

    // ---- preprocessing: CSR + W split/transpose ----
    cudaMemsetAsync(cntPtr, 0, N_NODES * sizeof(int));
    cudaMemsetAsync(totPtr, 0, sizeof(int));
    hist_kernel<<<edgeBlocks, TB>>>(ei);
    alloc_kernel<<<nodeBlocks, TB>>>();
    scatter_kernel<<<edgeBlocks, TB>>>(ei);
    wprep_kernel<<<(128*64  + TB - 1)/TB, TB>>>(W1, 128, 64,  wo1);
    wprep_kernel<<<(64*128  + TB - 1)/TB, TB>>>(W2, 64,  128, wo2);
    wprep_kernel<<<(128*256 + TB - 1)/TB, TB>>>(W3, 128, 256, wo3);
    wprep_kernel<<<(256*128 + TB - 1)/TB, TB>>>(W4, 256, 128, wo4);
    wprep_kernel<<<(128*64  + TB - 1)/TB, TB>>>(W5, 128, 64,  wo5);
    wprep_kernel<<<(64*64   + TB - 1)/TB, TB>>>(W6, 64,  64,  wo6);

    // L1: hs = dinv .* (x@W1); agg: dinv.*relu(dinv*sum + b1)  [prescaled for L2]
    mma_gemm_kernel<0,1><<<dim3(gemmRows, 1), TB>>>(x, whi + wo1, wlo + wo1, nullptr, bufA, 128, 64);
    agg64_kernel<1,1><<<aggBlocks, TB>>>(bufA, bufB, b1);

    // L2: agg -> GEMM bias+relu+scale (prescaled for L3 agg)
    agg64_kernel<0,0><<<aggBlocks, TB>>>(bufB, bufA, nullptr);
    mma_gemm_kernel<1,1><<<dim3(gemmRows, 2), TB>>>(bufA, whi + wo2, wlo + wo2, b2, bufB, 64, 128);

    // L3: agg -> GEMM bias+relu (no scale; L4 is GEMM-first)
    agg128_kernel<0,0><<<aggBlocks, TB>>>(bufB, bufA, nullptr);
    mma_gemm_kernel<1,0><<<dim3(gemmRows, 4), TB>>>(bufA, whi + wo3, wlo + wo3, b3, bufB, 128, 256);

    // L4: GEMM scale -> agg relu+b4
    mma_gemm_kernel<0,1><<<dim3(gemmRows, 2), TB>>>(bufB, whi + wo4, wlo + wo4, nullptr, bufA, 256, 128);
    agg128_kernel<1,0><<<aggBlocks, TB>>>(bufA, bufB, b4);

    // L5: GEMM scale -> agg relu+b5
    mma_gemm_kernel<0,1><<<dim3(gemmRows, 1), TB>>>(bufB, whi + wo5, wlo + wo5, nullptr, bufA, 128, 64);
    agg64_kernel<1,0><<<aggBlocks, TB>>>(bufA, bufB, b5);

    // L6: GEMM scale -> agg sigmoid+b6 -> d_out
    mma_gemm_kernel<0,1><<<dim3(gemmRows, 1), TB>>>(bufB, whi + wo6, wlo + wo6, nullptr, bufA, 64, 64);
    agg64_kernel<2,0><<<aggBlocks, TB>>>(bufA, out, b6);
}

// round 11
// speedup vs baseline: 1.3915x; 1.0234x over previous
#include <cuda_runtime.h>
#include <cuda_bf16.h>
#include <math.h>
#include <stdint.h>

#define N_NODES 50000
#define N_EDGES 800000
#define W_TOTAL 94208  // sum of K*Dout over 6 layers

// ---------------- static device scratch (allocation-free rule) ----------------
__device__ float g_bufA[N_NODES * 256];
__device__ float g_bufB[N_NODES * 256];
__device__ int   g_rowbeg[N_NODES];
__device__ int   g_rowend[N_NODES];
__device__ int   g_cursor[N_NODES];
__device__ int   g_cnt[N_NODES];
__device__ float g_dinv[N_NODES];
__device__ int   g_col[N_EDGES];
__device__ int   g_total;
__device__ unsigned short g_whi[W_TOTAL];  // bf16 hi, transposed [Dout][K]
__device__ unsigned short g_wlo[W_TOTAL];  // bf16 lo

// ---------------- CSR build (scan-free) ----------------
__global__ void hist_kernel(const int* __restrict__ ei) {
    int e = blockIdx.x * blockDim.x + threadIdx.x;
    if (e < N_EDGES) atomicAdd(&g_cnt[ei[N_EDGES + e]], 1);
}

__global__ void alloc_kernel() {
    int i = blockIdx.x * blockDim.x + threadIdx.x;
    if (i < N_NODES) {
        int c = g_cnt[i];
        g_dinv[i] = rsqrtf((float)c + 1.0f);
        int beg = atomicAdd(&g_total, c);
        g_rowbeg[i] = beg;
        g_rowend[i] = beg + c;
        g_cursor[i] = beg;
    }
}

__global__ void scatter_kernel(const int* __restrict__ ei) {
    int e = blockIdx.x * blockDim.x + threadIdx.x;
    if (e < N_EDGES) {
        int s = ei[e];
        int d = ei[N_EDGES + e];
        int pos = atomicAdd(&g_cursor[d], 1);
        g_col[pos] = s;
    }
}

// ---------------- W prep (ALL layers in ONE launch) ----------------
// fp32 [K][Dout] -> bf16 hi/lo transposed [Dout][K], flat index over W_TOTAL
__global__ void wprep_all_kernel(
    const float* __restrict__ W1, const float* __restrict__ W2,
    const float* __restrict__ W3, const float* __restrict__ W4,
    const float* __restrict__ W5, const float* __restrict__ W6) {
    int i = blockIdx.x * blockDim.x + threadIdx.x;
    if (i >= W_TOTAL) return;
    const float* W; int off, K, Dout;
    if      (i < 8192)  { W = W1; off = 0;     K = 128; Dout = 64;  }
    else if (i < 16384) { W = W2; off = 8192;  K = 64;  Dout = 128; }
    else if (i < 49152) { W = W3; off = 16384; K = 128; Dout = 256; }
    else if (i < 81920) { W = W4; off = 49152; K = 256; Dout = 128; }
    else if (i < 90112) { W = W5; off = 81920; K = 128; Dout = 64;  }
    else                { W = W6; off = 90112; K = 64;  Dout = 64;  }
    int local = i - off;
    int k = local / Dout, n = local % Dout;
    float v = W[local];
    __nv_bfloat16 h = __float2bfloat16(v);
    float r = v - __bfloat162float(h);
    g_whi[off + n * K + k] = __bfloat16_as_ushort(h);
    g_wlo[off + n * K + k] = __bfloat16_as_ushort(__float2bfloat16(r));
}

// ---------------- warp MMA: m16n8k16 bf16 -> fp32 (sm_80+ PTX) ----------
__device__ __forceinline__ void mma16816(float* d, const uint32_t* a, const uint32_t* b) {
    asm volatile(
        "mma.sync.aligned.m16n8k16.row.col.f32.bf16.bf16.f32 "
        "{%0,%1,%2,%3}, {%4,%5,%6,%7}, {%8,%9}, {%0,%1,%2,%3};"
        : "+f"(d[0]), "+f"(d[1]), "+f"(d[2]), "+f"(d[3])
        : "r"(a[0]), "r"(a[1]), "r"(a[2]), "r"(a[3]), "r"(b[0]), "r"(b[1]));
}

// ---------------- tensor-core GEMM: C = A[NxK] @ W[KxDout] (bf16-split, 3 MMAs) ----------
// BM=128, BN template (64 or 128), BK=32. 8 warps: warpRow 0..3 (32 rows),
// warpCol 0..1 (BN/2 cols, NF=BN/16 n-frags). k-permuted contiguous fragment loads.
template <int BN, int ACT, int SCALE>  // ACT: 0 none, 1 relu; SCALE: mult by dinv[row]
__global__ void __launch_bounds__(256) mma_gemm_kernel(
    const float* __restrict__ A,
    const unsigned short* __restrict__ whi, const unsigned short* __restrict__ wlo,
    const float* __restrict__ bias, float* __restrict__ C,
    int K, int Dout) {
    constexpr int BK = 32;
    constexpr int SA = 40;   // row stride in halves (80B)
    constexpr int NF = BN / 16;
    __shared__ __align__(16) unsigned short Ah[128 * SA];
    __shared__ __align__(16) unsigned short Al[128 * SA];
    __shared__ __align__(16) unsigned short Bh[BN * SA];
    __shared__ __align__(16) unsigned short Bl[BN * SA];

    const int t = threadIdx.x;
    const int lane = t & 31, wid = t >> 5;
    const int g = lane >> 2, tc = lane & 3;
    const int warpRow = wid & 3, warpCol = wid >> 2;
    const int rowBase = blockIdx.x * 128;
    const int colBase = blockIdx.y * BN;

    float d[2][NF][4] = {};

    for (int kb = 0; kb < K; kb += BK) {
        // ---- stage A tile [128][BK] with fused fp32 -> bf16 hi/lo split ----
        for (int task = t; task < 128 * (BK / 8); task += 256) {
            int row = task >> 2;             // BK/8 == 4
            int col0 = (task & 3) * 8;
            float v[8];
            int grow = rowBase + row;
            if (grow < N_NODES) {
                const float* p = A + (size_t)grow * K + kb + col0;
                float4 x0 = *reinterpret_cast<const float4*>(p);
                float4 x1 = *reinterpret_cast<const float4*>(p + 4);
                v[0]=x0.x; v[1]=x0.y; v[2]=x0.z; v[3]=x0.w;
                v[4]=x1.x; v[5]=x1.y; v[6]=x1.z; v[7]=x1.w;
            } else {
                #pragma unroll
                for (int j = 0; j < 8; j++) v[j] = 0.f;
            }
            unsigned int hp[4], lp[4];
            #pragma unroll
            for (int j = 0; j < 4; j++) {
                __nv_bfloat16 h0 = __float2bfloat16(v[2*j]);
                __nv_bfloat16 h1 = __float2bfloat16(v[2*j+1]);
                float r0 = v[2*j]   - __bfloat162float(h0);
                float r1 = v[2*j+1] - __bfloat162float(h1);
                hp[j] = (unsigned int)__bfloat16_as_ushort(h0)
                      | ((unsigned int)__bfloat16_as_ushort(h1) << 16);
                lp[j] = (unsigned int)__bfloat16_as_ushort(__float2bfloat16(r0))
                      | ((unsigned int)__bfloat16_as_ushort(__float2bfloat16(r1)) << 16);
            }
            *reinterpret_cast<uint4*>(&Ah[row * SA + col0]) = make_uint4(hp[0],hp[1],hp[2],hp[3]);
            *reinterpret_cast<uint4*>(&Al[row * SA + col0]) = make_uint4(lp[0],lp[1],lp[2],lp[3]);
        }
        // ---- stage B tile [BN][BK] from pre-split W^T ([Dout][K] bf16) ----
        for (int task = t; task < BN * (BK / 8); task += 256) {
            int n = task >> 2;
            int col0 = (task & 3) * 8;
            size_t src = (size_t)(colBase + n) * K + kb + col0;
            *reinterpret_cast<uint4*>(&Bh[n * SA + col0]) =
                *reinterpret_cast<const uint4*>(whi + src);
            *reinterpret_cast<uint4*>(&Bl[n * SA + col0]) =
                *reinterpret_cast<const uint4*>(wlo + src);
        }
        __syncthreads();

        #pragma unroll
        for (int ks = 0; ks < 2; ks++) {
            const int kk = ks * 16;
            uint32_t ahf[2][4], alf[2][4];
            #pragma unroll
            for (int i = 0; i < 2; i++) {
                int r0 = warpRow * 32 + i * 16 + g;
                uint2 x = *reinterpret_cast<const uint2*>(&Ah[r0 * SA + kk + tc * 4]);
                uint2 y = *reinterpret_cast<const uint2*>(&Ah[(r0 + 8) * SA + kk + tc * 4]);
                ahf[i][0] = x.x; ahf[i][2] = x.y; ahf[i][1] = y.x; ahf[i][3] = y.y;
                uint2 xl = *reinterpret_cast<const uint2*>(&Al[r0 * SA + kk + tc * 4]);
                uint2 yl = *reinterpret_cast<const uint2*>(&Al[(r0 + 8) * SA + kk + tc * 4]);
                alf[i][0] = xl.x; alf[i][2] = xl.y; alf[i][1] = yl.x; alf[i][3] = yl.y;
            }
            #pragma unroll
            for (int j = 0; j < NF; j++) {
                int n = warpCol * (BN / 2) + j * 8 + g;
                uint32_t bhf[2], blf[2];
                uint2 x = *reinterpret_cast<const uint2*>(&Bh[n * SA + kk + tc * 4]);
                bhf[0] = x.x; bhf[1] = x.y;
                uint2 y = *reinterpret_cast<const uint2*>(&Bl[n * SA + kk + tc * 4]);
                blf[0] = y.x; blf[1] = y.y;
                #pragma unroll
                for (int i = 0; i < 2; i++) {
                    mma16816(d[i][j], ahf[i], bhf);
                    mma16816(d[i][j], alf[i], bhf);
                    mma16816(d[i][j], ahf[i], blf);
                }
            }
        }
        __syncthreads();
    }

    // ---- epilogue: d frag (i,j): rows r0,r0+8; cols col,col+1 ----
    #pragma unroll
    for (int i = 0; i < 2; i++) {
        int r0 = rowBase + warpRow * 32 + i * 16 + g;
        int r1 = r0 + 8;
        float s0 = 1.0f, s1 = 1.0f;
        if (SCALE) {
            if (r0 < N_NODES) s0 = g_dinv[r0];
            if (r1 < N_NODES) s1 = g_dinv[r1];
        }
        #pragma unroll
        for (int j = 0; j < NF; j++) {
            int col = colBase + warpCol * (BN / 2) + j * 8 + tc * 2;
            float b0 = 0.f, b1 = 0.f;
            if (bias) { b0 = bias[col]; b1 = bias[col + 1]; }
            float v0 = d[i][j][0] + b0, v1 = d[i][j][1] + b1;
            float v2 = d[i][j][2] + b0, v3 = d[i][j][3] + b1;
            if (ACT == 1) {
                v0 = fmaxf(v0, 0.f); v1 = fmaxf(v1, 0.f);
                v2 = fmaxf(v2, 0.f); v3 = fmaxf(v3, 0.f);
            }
            if (r0 < N_NODES)
                *reinterpret_cast<float2*>(&C[(size_t)r0 * Dout + col]) =
                    make_float2(v0 * s0, v1 * s0);
            if (r1 < N_NODES)
                *reinterpret_cast<float2*>(&C[(size_t)r1 * Dout + col]) =
                    make_float2(v2 * s1, v3 * s1);
        }
    }
}

// ---------------- Aggregation (separable norm) ----------------
template <int ACT, int PRESCALE>  // ACT: 0 none, 1 relu, 2 sigmoid
__global__ void __launch_bounds__(256) agg64_kernel(
    const float* __restrict__ in, float* __restrict__ out,
    const float* __restrict__ bias) {
    int warp = (blockIdx.x * blockDim.x + threadIdx.x) >> 5;
    if (warp >= N_NODES) return;
    int lane = threadIdx.x & 31;
    const int off = lane * 2;

    float2 self = *reinterpret_cast<const float2*>(in + (size_t)warp * 64 + off);
    float ax = self.x, ay = self.y;

    int e = g_rowbeg[warp], end = g_rowend[warp];
    for (; e + 4 <= end; e += 4) {
        int s0 = g_col[e], s1 = g_col[e+1], s2 = g_col[e+2], s3 = g_col[e+3];
        float2 p0 = *reinterpret_cast<const float2*>(in + (size_t)s0 * 64 + off);
        float2 p1 = *reinterpret_cast<const float2*>(in + (size_t)s1 * 64 + off);
        float2 p2 = *reinterpret_cast<const float2*>(in + (size_t)s2 * 64 + off);
        float2 p3 = *reinterpret_cast<const float2*>(in + (size_t)s3 * 64 + off);
        ax += p0.x; ay += p0.y;
        ax += p1.x; ay += p1.y;
        ax += p2.x; ay += p2.y;
        ax += p3.x; ay += p3.y;
    }
    for (; e < end; e++) {
        int si = g_col[e];
        float2 p = *reinterpret_cast<const float2*>(in + (size_t)si * 64 + off);
        ax += p.x; ay += p.y;
    }

    float dd = g_dinv[warp];
    ax *= dd; ay *= dd;
    if (bias) {
        const float2 b = *reinterpret_cast<const float2*>(bias + off);
        ax += b.x; ay += b.y;
    }
    if (ACT == 1) { ax = fmaxf(ax, 0.f); ay = fmaxf(ay, 0.f); }
    if (ACT == 2) {
        ax = 1.0f / (1.0f + expf(-ax));
        ay = 1.0f / (1.0f + expf(-ay));
    }
    if (PRESCALE) { ax *= dd; ay *= dd; }
    *reinterpret_cast<float2*>(out + (size_t)warp * 64 + off) = make_float2(ax, ay);
}

template <int ACT, int PRESCALE>
__global__ void __launch_bounds__(256) agg128_kernel(
    const float* __restrict__ in, float* __restrict__ out,
    const float* __restrict__ bias) {
    int warp = (blockIdx.x * blockDim.x + threadIdx.x) >> 5;
    if (warp >= N_NODES) return;
    int lane = threadIdx.x & 31;
    const int off = lane * 4;

    float4 self = *reinterpret_cast<const float4*>(in + (size_t)warp * 128 + off);
    float ax = self.x, ay = self.y, az = self.z, aw = self.w;

    int e = g_rowbeg[warp], end = g_rowend[warp];
    for (; e + 4 <= end; e += 4) {
        int s0 = g_col[e], s1 = g_col[e+1], s2 = g_col[e+2], s3 = g_col[e+3];
        float4 p0 = *reinterpret_cast<const float4*>(in + (size_t)s0 * 128 + off);
        float4 p1 = *reinterpret_cast<const float4*>(in + (size_t)s1 * 128 + off);
        float4 p2 = *reinterpret_cast<const float4*>(in + (size_t)s2 * 128 + off);
        float4 p3 = *reinterpret_cast<const float4*>(in + (size_t)s3 * 128 + off);
        ax += p0.x; ay += p0.y; az += p0.z; aw += p0.w;
        ax += p1.x; ay += p1.y; az += p1.z; aw += p1.w;
        ax += p2.x; ay += p2.y; az += p2.z; aw += p2.w;
        ax += p3.x; ay += p3.y; az += p3.z; aw += p3.w;
    }
    for (; e < end; e++) {
        int si = g_col[e];
        float4 p = *reinterpret_cast<const float4*>(in + (size_t)si * 128 + off);
        ax += p.x; ay += p.y; az += p.z; aw += p.w;
    }

    float dd = g_dinv[warp];
    ax *= dd; ay *= dd; az *= dd; aw *= dd;
    if (bias) {
        const float4 b = *reinterpret_cast<const float4*>(bias + off);
        ax += b.x; ay += b.y; az += b.z; aw += b.w;
    }
    if (ACT == 1) {
        ax = fmaxf(ax, 0.f); ay = fmaxf(ay, 0.f);
        az = fmaxf(az, 0.f); aw = fmaxf(aw, 0.f);
    }
    if (ACT == 2) {
        ax = 1.0f/(1.0f+expf(-ax)); ay = 1.0f/(1.0f+expf(-ay));
        az = 1.0f/(1.0f+expf(-az)); aw = 1.0f/(1.0f+expf(-aw));
    }
    if (PRESCALE) { ax *= dd; ay *= dd; az *= dd; aw *= dd; }
    *reinterpret_cast<float4*>(out + (size_t)warp * 128 + off) = make_float4(ax, ay, az, aw);
}

// ---------------- launch ----------------
extern "C" void kernel_launch(void* const* d_in, const int* in_sizes, int n_in,
                              void* d_out, int out_size) {
    const float* x  = (const float*)d_in[0];
    const int*   ei = (const int*)d_in[1];   // int32! (JAX x64 disabled)
    const float* W1 = (const float*)d_in[2],  *b1 = (const float*)d_in[3];
    const float* W2 = (const float*)d_in[4],  *b2 = (const float*)d_in[5];
    const float* W3 = (const float*)d_in[6],  *b3 = (const float*)d_in[7];
    const float* W4 = (const float*)d_in[8],  *b4 = (const float*)d_in[9];
    const float* W5 = (const float*)d_in[10], *b5 = (const float*)d_in[11];
    const float* W6 = (const float*)d_in[12], *b6 = (const float*)d_in[13];
    float* out = (float*)d_out;

    float *bufA, *bufB;
    cudaGetSymbolAddress((void**)&bufA, g_bufA);
    cudaGetSymbolAddress((void**)&bufB, g_bufB);
    void *cntPtr, *totPtr;
    cudaGetSymbolAddress(&cntPtr, g_cnt);
    cudaGetSymbolAddress(&totPtr, g_total);
    unsigned short *whi, *wlo;
    cudaGetSymbolAddress((void**)&whi, g_whi);
    cudaGetSymbolAddress((void**)&wlo, g_wlo);

    const int TB = 256;
    const int nodeBlocks = (N_NODES + TB - 1) / TB;
    const int edgeBlocks = (N_EDGES + TB - 1) / TB;
    const int aggBlocks  = (N_NODES * 32 + TB - 1) / TB;
    const int gemmRows   = (N_NODES + 127) / 128;

    // W layer offsets within g_whi/g_wlo
    const int wo1 = 0, wo2 = 8192, wo3 = 16384, wo4 = 49152, wo5 = 81920, wo6 = 90112;

    // ---- preprocessing: CSR + W split/transpose (single launch) ----
    cudaMemsetAsync(cntPtr, 0, N_NODES * sizeof(int));
    cudaMemsetAsync(totPtr, 0, sizeof(int));
    hist_kernel<<<edgeBlocks, TB>>>(ei);
    alloc_kernel<<<nodeBlocks, TB>>>();
    scatter_kernel<<<edgeBlocks, TB>>>(ei);
    wprep_all_kernel<<<(W_TOTAL + TB - 1) / TB, TB>>>(W1, W2, W3, W4, W5, W6);

    // L1: hs = dinv .* (x@W1); agg: dinv.*relu(dinv*sum + b1)  [prescaled for L2]
    mma_gemm_kernel<64,0,1><<<dim3(gemmRows, 1), TB>>>(x, whi + wo1, wlo + wo1, nullptr, bufA, 128, 64);
    agg64_kernel<1,1><<<aggBlocks, TB>>>(bufA, bufB, b1);

    // L2: agg -> GEMM bias+relu+scale (prescaled for L3 agg)   BN=128, single y-pass
    agg64_kernel<0,0><<<aggBlocks, TB>>>(bufB, bufA, nullptr);
    mma_gemm_kernel<128,1,1><<<dim3(gemmRows, 1), TB>>>(bufA, whi + wo2, wlo + wo2, b2, bufB, 64, 128);

    // L3: agg -> GEMM bias+relu (no scale; L4 is GEMM-first)   BN=128, 2 y-passes
    agg128_kernel<0,0><<<aggBlocks, TB>>>(bufB, bufA, nullptr);
    mma_gemm_kernel<128,1,0><<<dim3(gemmRows, 2), TB>>>(bufA, whi + wo3, wlo + wo3, b3, bufB, 128, 256);

    // L4: GEMM scale -> agg relu+b4                            BN=128, single y-pass
    mma_gemm_kernel<128,0,1><<<dim3(gemmRows, 1), TB>>>(bufB, whi + wo4, wlo + wo4, nullptr, bufA, 256, 128);
    agg128_kernel<1,0><<<aggBlocks, TB>>>(bufA, bufB, b4);

    // L5: GEMM scale -> agg relu+b5
    mma_gemm_kernel<64,0,1><<<dim3(gemmRows, 1), TB>>>(bufB, whi + wo5, wlo + wo5, nullptr, bufA, 128, 64);
    agg64_kernel<1,0><<<aggBlocks, TB>>>(bufA, bufB, b5);

    // L6: GEMM scale -> agg sigmoid+b6 -> d_out
    mma_gemm_kernel<64,0,1><<<dim3(gemmRows, 1), TB>>>(bufB, whi + wo6, wlo + wo6, nullptr, bufA, 64, 64);
    agg64_kernel<2,0><<<aggBlocks, TB>>>(bufA, out, b6);
}